// round 1
// baseline (speedup 1.0000x reference)
#include <cuda_runtime.h>
#include <math.h>

#define BATCH 2
#define SEQ   2048
#define DM    2048
#define NH    16
#define DKH   128
#define MTOT  (BATCH*SEQ)   // 4096

// ---- scratch (device globals; no allocation allowed) ----
__device__ float g_q[BATCH*NH*SEQ*DKH];
__device__ float g_k[BATCH*NH*SEQ*DKH];
__device__ float g_v[BATCH*NH*SEQ*DKH];
__device__ float g_ctx[BATCH*SEQ*DM];

// ============================================================
// GEMM: C = A @ W^T (+bias).  A[M,K] row-major, W[N,K] row-major.
// BM=BN=128, BK=8, 256 threads, 8x8 per thread.
// MODE 0: plain C[m*DM+n] + bias[n]
// MODE 1: qkv layout  C[((b*NH+h)*SEQ+s)*DKH + dk]
// ============================================================
template<int MODE>
__global__ __launch_bounds__(256)
void gemm_kernel(const float* __restrict__ A, const float* __restrict__ W,
                 const float* __restrict__ bias, float* __restrict__ C)
{
    const int K = DM;
    __shared__ float As[8][128];
    __shared__ float Bs[8][128];

    int bm = blockIdx.y * 128;
    int bn = blockIdx.x * 128;
    int tid = threadIdx.x;
    int tx = tid & 15, ty = tid >> 4;

    int lrow = tid >> 1;          // 0..127
    int lk4  = (tid & 1) * 4;     // 0 or 4

    const float* Aptr = A + (size_t)(bm + lrow) * K + lk4;
    const float* Wptr = W + (size_t)(bn + lrow) * K + lk4;

    float acc[8][8];
#pragma unroll
    for (int i = 0; i < 8; i++)
#pragma unroll
        for (int j = 0; j < 8; j++) acc[i][j] = 0.f;

    for (int k0 = 0; k0 < K; k0 += 8) {
        float4 av = *(const float4*)(Aptr + k0);
        float4 wv = *(const float4*)(Wptr + k0);
        As[lk4+0][lrow] = av.x; As[lk4+1][lrow] = av.y;
        As[lk4+2][lrow] = av.z; As[lk4+3][lrow] = av.w;
        Bs[lk4+0][lrow] = wv.x; Bs[lk4+1][lrow] = wv.y;
        Bs[lk4+2][lrow] = wv.z; Bs[lk4+3][lrow] = wv.w;
        __syncthreads();

#pragma unroll
        for (int kk = 0; kk < 8; kk++) {
            float a[8], b[8];
            float4 a0 = *(const float4*)&As[kk][ty*8];
            float4 a1 = *(const float4*)&As[kk][ty*8+4];
            float4 b0 = *(const float4*)&Bs[kk][tx*8];
            float4 b1 = *(const float4*)&Bs[kk][tx*8+4];
            a[0]=a0.x; a[1]=a0.y; a[2]=a0.z; a[3]=a0.w;
            a[4]=a1.x; a[5]=a1.y; a[6]=a1.z; a[7]=a1.w;
            b[0]=b0.x; b[1]=b0.y; b[2]=b0.z; b[3]=b0.w;
            b[4]=b1.x; b[5]=b1.y; b[6]=b1.z; b[7]=b1.w;
#pragma unroll
            for (int i = 0; i < 8; i++)
#pragma unroll
                for (int j = 0; j < 8; j++)
                    acc[i][j] += a[i] * b[j];
        }
        __syncthreads();
    }

#pragma unroll
    for (int i = 0; i < 8; i++) {
        int m = bm + ty*8 + i;
#pragma unroll
        for (int j = 0; j < 8; j++) {
            int n = bn + tx*8 + j;
            if (MODE == 0) {
                C[(size_t)m*DM + n] = acc[i][j] + bias[n];
            } else {
                int b  = m >> 11;          // /SEQ
                int s  = m & (SEQ-1);
                int h  = n >> 7;           // /DKH
                int dk = n & (DKH-1);
                C[(((size_t)(b*NH + h))*SEQ + s)*DKH + dk] = acc[i][j];
            }
        }
    }
}

// ============================================================
// RoPE on g_q and g_k (layout [b][h][s][dk])
// ============================================================
__global__ __launch_bounds__(256)
void rope_kernel()
{
    int idx = blockIdx.x * blockDim.x + threadIdx.x;
    const int total = BATCH*NH*SEQ*64;          // pairs per tensor
    if (idx >= total) return;
    int i  = idx & 63;                 // pair index within head dim
    int s  = (idx >> 6) & (SEQ-1);
    int bh = idx >> 17;                // 64*2048 = 2^17
    size_t base = ((size_t)bh*SEQ + s)*DKH + 2*i;

    float freq = powf(10000.f, -((float)(2*i)) / 128.f);
    float ang  = (float)s * freq;
    float sn, cs;
    sincosf(ang, &sn, &cs);

    float qe = g_q[base], qo = g_q[base+1];
    g_q[base]   = qe*cs - qo*sn;
    g_q[base+1] = qe*sn + qo*cs;
    float ke = g_k[base], ko = g_k[base+1];
    g_k[base]   = ke*cs - ko*sn;
    g_k[base+1] = ke*sn + ko*cs;
}

// ============================================================
// Flash attention fp32, causal.  BM=64 q-rows, BN=64 kv-rows.
// grid: (SEQ/64, BATCH*NH), 256 threads, dynamic smem 116224 B.
// ============================================================
#define ATTN_SMEM_FLOATS 29056
#define ATTN_SMEM_BYTES  (ATTN_SMEM_FLOATS*4)

__global__ __launch_bounds__(256)
void attn_kernel(const float* __restrict__ Q, const float* __restrict__ K,
                 const float* __restrict__ V, float* __restrict__ ctx)
{
    extern __shared__ float smem[];
    float* sQ    = smem;            // 64 x 129
    float* sK    = smem + 8256;     // 64 x 129
    float* sV    = smem + 16512;    // 64 x 128 (float4-aligned rows)
    float* sP    = smem + 24704;    // 64 x 65
    float* sM    = smem + 28864;    // 64
    float* sL    = smem + 28928;    // 64
    float* sCorr = smem + 28992;    // 64

    int qt  = blockIdx.x;
    int bh  = blockIdx.y;
    int tid = threadIdx.x;
    int warp = tid >> 5, lane = tid & 31;
    int tx = tid & 15, ty = tid >> 4;

    const float* Qb = Q + (size_t)bh * SEQ * DKH;
    const float* Kb = K + (size_t)bh * SEQ * DKH;
    const float* Vb = V + (size_t)bh * SEQ * DKH;

    // load Q tile (rows qt*64 .. qt*64+63)
    {
        const float4* src = (const float4*)(Qb + (size_t)qt*64*DKH);
        for (int i = tid; i < 64*DKH/4; i += 256) {
            float4 v = src[i];
            int r = i >> 5;          // 32 float4 per row
            int c = (i & 31) * 4;
            sQ[r*129 + c+0] = v.x; sQ[r*129 + c+1] = v.y;
            sQ[r*129 + c+2] = v.z; sQ[r*129 + c+3] = v.w;
        }
    }
    if (tid < 64) { sM[tid] = -1e30f; sL[tid] = 0.f; }

    float o[8][4];
#pragma unroll
    for (int r = 0; r < 8; r++)
#pragma unroll
        for (int c = 0; c < 4; c++) o[r][c] = 0.f;

    const float scl = 0.08838834764831845f;  // 1/sqrt(128)

    for (int kt = 0; kt <= qt; ++kt) {
        __syncthreads();   // prior PV done (and Q load on first iter)

        // load K, V tiles
        {
            const float4* ksrc = (const float4*)(Kb + (size_t)kt*64*DKH);
            const float4* vsrc = (const float4*)(Vb + (size_t)kt*64*DKH);
            for (int i = tid; i < 64*DKH/4; i += 256) {
                int r = i >> 5;
                int c = (i & 31) * 4;
                float4 kv = ksrc[i];
                sK[r*129 + c+0] = kv.x; sK[r*129 + c+1] = kv.y;
                sK[r*129 + c+2] = kv.z; sK[r*129 + c+3] = kv.w;
                float4 vv = vsrc[i];
                *(float4*)&sV[r*128 + c] = vv;
            }
        }
        __syncthreads();

        // S = Q K^T : each thread 4x4 (rows ty*4.., cols tx*4..)
        float acc[4][4];
#pragma unroll
        for (int i = 0; i < 4; i++)
#pragma unroll
            for (int j = 0; j < 4; j++) acc[i][j] = 0.f;

        const float* q0 = sQ + (ty*4+0)*129;
        const float* q1 = sQ + (ty*4+1)*129;
        const float* q2 = sQ + (ty*4+2)*129;
        const float* q3 = sQ + (ty*4+3)*129;
        const float* k0 = sK + (tx*4+0)*129;
        const float* k1 = sK + (tx*4+1)*129;
        const float* k2 = sK + (tx*4+2)*129;
        const float* k3 = sK + (tx*4+3)*129;
#pragma unroll 8
        for (int k = 0; k < DKH; ++k) {
            float a0 = q0[k], a1 = q1[k], a2 = q2[k], a3 = q3[k];
            float b0 = k0[k], b1 = k1[k], b2 = k2[k], b3 = k3[k];
            acc[0][0] += a0*b0; acc[0][1] += a0*b1; acc[0][2] += a0*b2; acc[0][3] += a0*b3;
            acc[1][0] += a1*b0; acc[1][1] += a1*b1; acc[1][2] += a1*b2; acc[1][3] += a1*b3;
            acc[2][0] += a2*b0; acc[2][1] += a2*b1; acc[2][2] += a2*b2; acc[2][3] += a2*b3;
            acc[3][0] += a3*b0; acc[3][1] += a3*b1; acc[3][2] += a3*b2; acc[3][3] += a3*b3;
        }
        // mask + scale + store raw scores
        int qg0 = qt*64 + ty*4;
        int kg0 = kt*64 + tx*4;
#pragma unroll
        for (int i = 0; i < 4; i++)
#pragma unroll
            for (int j = 0; j < 4; j++) {
                float s = acc[i][j] * scl;
                if (kg0 + j > qg0 + i) s = -1e30f;
                sP[(ty*4+i)*65 + tx*4 + j] = s;
            }
        __syncthreads();

        // per-row online softmax (64 rows, one thread each)
        if (tid < 64) {
            int r = tid;
            float mold = sM[r];
            float mx = mold;
#pragma unroll 8
            for (int j = 0; j < 64; ++j) mx = fmaxf(mx, sP[r*65 + j]);
            float corr = __expf(mold - mx);
            float sum = 0.f;
#pragma unroll 8
            for (int j = 0; j < 64; ++j) {
                float p = __expf(sP[r*65 + j] - mx);
                sP[r*65 + j] = p;
                sum += p;
            }
            sM[r] = mx;
            sL[r] = sL[r]*corr + sum;
            sCorr[r] = corr;
        }
        __syncthreads();

        // O scale + PV accumulate.  warp owns rows warp*8..+7, lane owns cols lane*4..+3
#pragma unroll
        for (int r8 = 0; r8 < 8; ++r8) {
            float corr = sCorr[warp*8 + r8];
            o[r8][0] *= corr; o[r8][1] *= corr; o[r8][2] *= corr; o[r8][3] *= corr;
        }
        for (int j = 0; j < 64; ++j) {
            float4 vv = *(const float4*)&sV[j*128 + lane*4];
#pragma unroll
            for (int r8 = 0; r8 < 8; ++r8) {
                float p = sP[(warp*8 + r8)*65 + j];
                o[r8][0] += p*vv.x; o[r8][1] += p*vv.y;
                o[r8][2] += p*vv.z; o[r8][3] += p*vv.w;
            }
        }
    }

    // final: divide by l, write ctx[b][s][h*128+dk]
    int b = bh / NH, h = bh % NH;
#pragma unroll
    for (int r8 = 0; r8 < 8; ++r8) {
        int row = qt*64 + warp*8 + r8;
        float inv = 1.0f / sL[warp*8 + r8];
        float4 res = make_float4(o[r8][0]*inv, o[r8][1]*inv, o[r8][2]*inv, o[r8][3]*inv);
        *(float4*)&ctx[((size_t)(b*SEQ + row))*DM + h*DKH + lane*4] = res;
    }
}

// ============================================================
extern "C" void kernel_launch(void* const* d_in, const int* in_sizes, int n_in,
                              void* d_out, int out_size)
{
    const float* x  = (const float*)d_in[0];
    const float* wq = (const float*)d_in[1];
    const float* wk = (const float*)d_in[2];
    const float* wv = (const float*)d_in[3];
    const float* wo = (const float*)d_in[4];
    const float* bo = (const float*)d_in[5];
    float* out = (float*)d_out;

    float *q, *k, *v, *ctx;
    cudaGetSymbolAddress((void**)&q,   g_q);
    cudaGetSymbolAddress((void**)&k,   g_k);
    cudaGetSymbolAddress((void**)&v,   g_v);
    cudaGetSymbolAddress((void**)&ctx, g_ctx);

    dim3 gg(DM/128, MTOT/128);   // (16, 32)

    gemm_kernel<1><<<gg, 256>>>(x, wq, nullptr, q);
    gemm_kernel<1><<<gg, 256>>>(x, wk, nullptr, k);
    gemm_kernel<1><<<gg, 256>>>(x, wv, nullptr, v);

    rope_kernel<<<(BATCH*NH*SEQ*64 + 255)/256, 256>>>();

    cudaFuncSetAttribute(attn_kernel, cudaFuncAttributeMaxDynamicSharedMemorySize,
                         ATTN_SMEM_BYTES);
    attn_kernel<<<dim3(SEQ/64, BATCH*NH), 256, ATTN_SMEM_BYTES>>>(q, k, v, ctx);

    gemm_kernel<0><<<gg, 256>>>(ctx, wo, bo, out);
}

// round 3
// speedup vs baseline: 1.8741x; 1.8741x over previous
#include <cuda_runtime.h>
#include <cuda_bf16.h>
#include <math.h>
#include <stdint.h>

#define BATCH 2
#define SEQ   2048
#define DM    2048
#define NH    16
#define DKH   128
#define MTOT  (BATCH*SEQ)   // 4096

// ---- scratch (device globals) ----
__device__ float g_q[MTOT*DM];
__device__ float g_k[MTOT*DM];
__device__ float g_v[MTOT*DM];
__device__ float g_ctx[MTOT*DM];
__device__ __nv_bfloat16 g_xh[MTOT*DM];
__device__ __nv_bfloat16 g_xl[MTOT*DM];
__device__ __nv_bfloat16 g_wh[4][DM*DM];
__device__ __nv_bfloat16 g_wl[4][DM*DM];
__device__ __nv_bfloat16 g_ch[MTOT*DM];
__device__ __nv_bfloat16 g_cl[MTOT*DM];

// ============================================================
// helpers
// ============================================================
__device__ __forceinline__ uint32_t smem_u32(const void* p) {
    uint32_t a;
    asm("{ .reg .u64 t; cvta.to.shared.u64 t, %1; cvt.u32.u64 %0, t; }" : "=r"(a) : "l"(p));
    return a;
}
__device__ __forceinline__ void cp_async16(uint32_t dst, const void* src) {
    asm volatile("cp.async.cg.shared.global [%0], [%1], 16;" :: "r"(dst), "l"(src));
}
__device__ __forceinline__ void cp_commit() {
    asm volatile("cp.async.commit_group;" ::: "memory");
}
template<int N>
__device__ __forceinline__ void cp_wait() {
    asm volatile("cp.async.wait_group %0;" :: "n"(N) : "memory");
}
__device__ __forceinline__ void ldsm_x4(uint32_t& r0, uint32_t& r1, uint32_t& r2, uint32_t& r3, uint32_t a) {
    asm volatile("ldmatrix.sync.aligned.m8n8.x4.shared.b16 {%0,%1,%2,%3}, [%4];"
                 : "=r"(r0), "=r"(r1), "=r"(r2), "=r"(r3) : "r"(a));
}
__device__ __forceinline__ void ldsm_x2(uint32_t& r0, uint32_t& r1, uint32_t a) {
    asm volatile("ldmatrix.sync.aligned.m8n8.x2.shared.b16 {%0,%1}, [%2];"
                 : "=r"(r0), "=r"(r1) : "r"(a));
}
__device__ __forceinline__ void mma_bf16(float* c, const uint32_t* a, const uint32_t* b) {
    asm volatile("mma.sync.aligned.m16n8k16.row.col.f32.bf16.bf16.f32 "
                 "{%0,%1,%2,%3}, {%4,%5,%6,%7}, {%8,%9}, {%0,%1,%2,%3};"
                 : "+f"(c[0]), "+f"(c[1]), "+f"(c[2]), "+f"(c[3])
                 : "r"(a[0]), "r"(a[1]), "r"(a[2]), "r"(a[3]), "r"(b[0]), "r"(b[1]));
}

// ============================================================
// Split fp32 -> bf16 hi/lo
// ============================================================
__global__ __launch_bounds__(256)
void split_kernel(const float* __restrict__ src, __nv_bfloat16* __restrict__ hi,
                  __nv_bfloat16* __restrict__ lo, int n4)
{
    int i = blockIdx.x * 256 + threadIdx.x;
    if (i >= n4) return;
    float4 v = ((const float4*)src)[i];
    __nv_bfloat16 h0 = __float2bfloat16(v.x), h1 = __float2bfloat16(v.y);
    __nv_bfloat16 h2 = __float2bfloat16(v.z), h3 = __float2bfloat16(v.w);
    __nv_bfloat16 l0 = __float2bfloat16(v.x - __bfloat162float(h0));
    __nv_bfloat16 l1 = __float2bfloat16(v.y - __bfloat162float(h1));
    __nv_bfloat16 l2 = __float2bfloat16(v.z - __bfloat162float(h2));
    __nv_bfloat16 l3 = __float2bfloat16(v.w - __bfloat162float(h3));
    ((__nv_bfloat162*)hi)[2*i]   = __nv_bfloat162(h0, h1);
    ((__nv_bfloat162*)hi)[2*i+1] = __nv_bfloat162(h2, h3);
    ((__nv_bfloat162*)lo)[2*i]   = __nv_bfloat162(l0, l1);
    ((__nv_bfloat162*)lo)[2*i+1] = __nv_bfloat162(l2, l3);
}

// ============================================================
// mma.sync GEMM: C[M,N] = A[M,K] @ W[N,K]^T  via bf16x3
// BM=128 BN=128 BK=32, 256 threads (8 warps, 2x4), warp 64x32.
// SMEM tiles padded: row stride 40 bf16 (80B).
// ============================================================
#define BM 128
#define BN 128
#define BK 32
#define TSTRIDE 40                      // bf16 elems per smem row
#define TILE_BYTES (128*TSTRIDE*2)      // 10240
#define STAGE_BYTES (4*TILE_BYTES)      // 40960: Ah Al Bh Bl
#define GEMM_SMEM (2*STAGE_BYTES)       // 81920

template<int ADD_BIAS>
__global__ __launch_bounds__(256, 2)
void gemm_mma(const __nv_bfloat16* __restrict__ Ah, const __nv_bfloat16* __restrict__ Al,
              const __nv_bfloat16* __restrict__ Bh, const __nv_bfloat16* __restrict__ Bl,
              const float* __restrict__ bias, float* __restrict__ C)
{
    extern __shared__ __align__(128) char gsm[];
    const uint32_t sb = smem_u32(gsm);
    const int tid = threadIdx.x, wid = tid >> 5, lane = tid & 31;
    const int bm = blockIdx.y * BM;
    const int bn = blockIdx.x * BN;
    const int warp_m = wid >> 2;        // 0..1  -> m offset *64
    const int warp_n = wid & 3;         // 0..3  -> n offset *32

    // smem offsets within a stage
    const uint32_t OFF_AH = 0, OFF_AL = TILE_BYTES, OFF_BH = 2*TILE_BYTES, OFF_BL = 3*TILE_BYTES;

    float acc[4][4][4];
#pragma unroll
    for (int i = 0; i < 4; i++)
#pragma unroll
        for (int j = 0; j < 4; j++)
#pragma unroll
            for (int r = 0; r < 4; r++) acc[i][j][r] = 0.f;

    // loader mapping: 512 cp.async16 per (array), thread does 2 per array.
    // i = tid*2 + {0,1}: row = i>>2 (0..127), seg = i&3 (16B seg of 64B row)
    auto issue_chunk = [&](int c, int buf) {
        uint32_t st = sb + buf * STAGE_BYTES;
        int k0 = c * BK;
#pragma unroll
        for (int t = 0; t < 2; ++t) {
            int i = tid * 2 + t;
            int row = i >> 2, seg = i & 3;
            uint32_t dst = (uint32_t)(row * (TSTRIDE*2) + seg * 16);
            const char* ah = (const char*)(Ah + (size_t)(bm + row)*DM + k0) + seg*16;
            const char* al = (const char*)(Al + (size_t)(bm + row)*DM + k0) + seg*16;
            const char* wh = (const char*)(Bh + (size_t)(bn + row)*DM + k0) + seg*16;
            const char* wl = (const char*)(Bl + (size_t)(bn + row)*DM + k0) + seg*16;
            cp_async16(st + OFF_AH + dst, ah);
            cp_async16(st + OFF_AL + dst, al);
            cp_async16(st + OFF_BH + dst, wh);
            cp_async16(st + OFF_BL + dst, wl);
        }
        cp_commit();
    };

    issue_chunk(0, 0);

    const int NCH = DM / BK;   // 64
    for (int c = 0; c < NCH; ++c) {
        int buf = c & 1;
        if (c + 1 < NCH) { issue_chunk(c + 1, buf ^ 1); cp_wait<1>(); }
        else             { cp_wait<0>(); }
        __syncthreads();

        uint32_t st = sb + buf * STAGE_BYTES;
        // fragment base addresses for this warp
        // A rows: warp_m*64 + am*16 + lane%16 ; col byte: kk*32 + (lane>>4)*16
        uint32_t a_row = (uint32_t)(warp_m*64 + (lane & 15));
        uint32_t a_colb = (uint32_t)((lane >> 4) * 16);
        // B rows: warp_n*32 + bt*8 + lane%8 ; col byte: kk*32 + ((lane>>3)&1)*16
        uint32_t b_row = (uint32_t)(warp_n*32 + (lane & 7));
        uint32_t b_colb = (uint32_t)(((lane >> 3) & 1) * 16);

#pragma unroll
        for (int kk = 0; kk < 2; ++kk) {
            uint32_t abase = st + a_row*(TSTRIDE*2) + kk*32 + a_colb;
            uint32_t bbase = st + b_row*(TSTRIDE*2) + kk*32 + b_colb;

            uint32_t ah[4][4], bh[4][2];
#pragma unroll
            for (int am = 0; am < 4; ++am)
                ldsm_x4(ah[am][0], ah[am][1], ah[am][2], ah[am][3],
                        abase + OFF_AH + am*16*(TSTRIDE*2));
#pragma unroll
            for (int bt = 0; bt < 4; ++bt)
                ldsm_x2(bh[bt][0], bh[bt][1], bbase + OFF_BH + bt*8*(TSTRIDE*2));
#pragma unroll
            for (int am = 0; am < 4; ++am)
#pragma unroll
                for (int bt = 0; bt < 4; ++bt)
                    mma_bf16(acc[am][bt], ah[am], bh[bt]);

            // Ah x Bl
            {
                uint32_t bl[4][2];
#pragma unroll
                for (int bt = 0; bt < 4; ++bt)
                    ldsm_x2(bl[bt][0], bl[bt][1], bbase + OFF_BL + bt*8*(TSTRIDE*2));
#pragma unroll
                for (int am = 0; am < 4; ++am)
#pragma unroll
                    for (int bt = 0; bt < 4; ++bt)
                        mma_bf16(acc[am][bt], ah[am], bl[bt]);
            }
            // Al x Bh
            {
                uint32_t al[4][4];
#pragma unroll
                for (int am = 0; am < 4; ++am)
                    ldsm_x4(al[am][0], al[am][1], al[am][2], al[am][3],
                            abase + OFF_AL + am*16*(TSTRIDE*2));
#pragma unroll
                for (int am = 0; am < 4; ++am)
#pragma unroll
                    for (int bt = 0; bt < 4; ++bt)
                        mma_bf16(acc[am][bt], al[am], bh[bt]);
            }
        }
        __syncthreads();
    }

    // epilogue
    const int m_base = bm + warp_m*64;
    const int n_base = bn + warp_n*32;
#pragma unroll
    for (int am = 0; am < 4; ++am) {
#pragma unroll
        for (int bt = 0; bt < 4; ++bt) {
            int col = n_base + bt*8 + (lane & 3)*2;
            int r0 = m_base + am*16 + (lane >> 2);
            float b0 = 0.f, b1 = 0.f;
            if (ADD_BIAS) { b0 = bias[col]; b1 = bias[col+1]; }
            float2 v0 = make_float2(acc[am][bt][0] + b0, acc[am][bt][1] + b1);
            float2 v1 = make_float2(acc[am][bt][2] + b0, acc[am][bt][3] + b1);
            *(float2*)(C + (size_t)r0*DM + col)       = v0;
            *(float2*)(C + (size_t)(r0+8)*DM + col)   = v1;
        }
    }
}

// ============================================================
// RoPE on g_q and g_k, layout [b][s][h*128+dk]
// ============================================================
__global__ __launch_bounds__(256)
void rope_kernel()
{
    int idx = blockIdx.x * blockDim.x + threadIdx.x;
    const int total = BATCH*NH*SEQ*64;
    if (idx >= total) return;
    int i  = idx & 63;
    int s  = (idx >> 6) & (SEQ-1);
    int bh = idx >> 17;
    int b = bh >> 4, h = bh & 15;
    size_t base = ((size_t)b*SEQ + s)*DM + h*DKH + 2*i;

    float freq = powf(10000.f, -((float)(2*i)) / 128.f);
    float ang  = (float)s * freq;
    float sn, cs;
    sincosf(ang, &sn, &cs);

    float qe = g_q[base], qo = g_q[base+1];
    g_q[base]   = qe*cs - qo*sn;
    g_q[base+1] = qe*sn + qo*cs;
    float ke = g_k[base], ko = g_k[base+1];
    g_k[base]   = ke*cs - ko*sn;
    g_k[base+1] = ke*sn + ko*cs;
}

// ============================================================
// Flash attention fp32, causal; QKV layout [b][s][h*128+dk]
// ============================================================
#define ATTN_SMEM_FLOATS 29056
#define ATTN_SMEM_BYTES  (ATTN_SMEM_FLOATS*4)

__global__ __launch_bounds__(256)
void attn_kernel(const float* __restrict__ Q, const float* __restrict__ K,
                 const float* __restrict__ V, float* __restrict__ ctx)
{
    extern __shared__ float smem[];
    float* sQ    = smem;            // 64 x 129
    float* sK    = smem + 8256;     // 64 x 129
    float* sV    = smem + 16512;    // 64 x 128
    float* sP    = smem + 24704;    // 64 x 65
    float* sM    = smem + 28864;
    float* sL    = smem + 28928;
    float* sCorr = smem + 28992;

    int qt  = blockIdx.x;
    int bh  = blockIdx.y;
    int tid = threadIdx.x;
    int warp = tid >> 5, lane = tid & 31;
    int tx = tid & 15, ty = tid >> 4;
    int b = bh / NH, h = bh % NH;

    const float* Qb = Q + ((size_t)b*SEQ + qt*64)*DM + h*DKH;
    const float* Kb = K + ((size_t)b*SEQ)*DM + h*DKH;
    const float* Vb = V + ((size_t)b*SEQ)*DM + h*DKH;

    for (int i = tid; i < 64*DKH/4; i += 256) {
        int r = i >> 5;
        int c = (i & 31) * 4;
        float4 v = *(const float4*)(Qb + (size_t)r*DM + c);
        sQ[r*129 + c+0] = v.x; sQ[r*129 + c+1] = v.y;
        sQ[r*129 + c+2] = v.z; sQ[r*129 + c+3] = v.w;
    }
    if (tid < 64) { sM[tid] = -1e30f; sL[tid] = 0.f; }

    float o[8][4];
#pragma unroll
    for (int r = 0; r < 8; r++)
#pragma unroll
        for (int c = 0; c < 4; c++) o[r][c] = 0.f;

    const float scl = 0.08838834764831845f;

    for (int kt = 0; kt <= qt; ++kt) {
        __syncthreads();
        for (int i = tid; i < 64*DKH/4; i += 256) {
            int r = i >> 5;
            int c = (i & 31) * 4;
            size_t row = (size_t)(kt*64 + r)*DM;
            float4 kv = *(const float4*)(Kb + row + c);
            sK[r*129 + c+0] = kv.x; sK[r*129 + c+1] = kv.y;
            sK[r*129 + c+2] = kv.z; sK[r*129 + c+3] = kv.w;
            float4 vv = *(const float4*)(Vb + row + c);
            *(float4*)&sV[r*128 + c] = vv;
        }
        __syncthreads();

        float acc[4][4];
#pragma unroll
        for (int i = 0; i < 4; i++)
#pragma unroll
            for (int j = 0; j < 4; j++) acc[i][j] = 0.f;

        const float* q0 = sQ + (ty*4+0)*129;
        const float* q1 = sQ + (ty*4+1)*129;
        const float* q2 = sQ + (ty*4+2)*129;
        const float* q3 = sQ + (ty*4+3)*129;
        const float* k0 = sK + (tx*4+0)*129;
        const float* k1 = sK + (tx*4+1)*129;
        const float* k2 = sK + (tx*4+2)*129;
        const float* k3 = sK + (tx*4+3)*129;
#pragma unroll 8
        for (int k = 0; k < DKH; ++k) {
            float a0 = q0[k], a1 = q1[k], a2 = q2[k], a3 = q3[k];
            float b0 = k0[k], b1 = k1[k], b2 = k2[k], b3 = k3[k];
            acc[0][0] += a0*b0; acc[0][1] += a0*b1; acc[0][2] += a0*b2; acc[0][3] += a0*b3;
            acc[1][0] += a1*b0; acc[1][1] += a1*b1; acc[1][2] += a1*b2; acc[1][3] += a1*b3;
            acc[2][0] += a2*b0; acc[2][1] += a2*b1; acc[2][2] += a2*b2; acc[2][3] += a2*b3;
            acc[3][0] += a3*b0; acc[3][1] += a3*b1; acc[3][2] += a3*b2; acc[3][3] += a3*b3;
        }
        int qg0 = qt*64 + ty*4;
        int kg0 = kt*64 + tx*4;
#pragma unroll
        for (int i = 0; i < 4; i++)
#pragma unroll
            for (int j = 0; j < 4; j++) {
                float s = acc[i][j] * scl;
                if (kg0 + j > qg0 + i) s = -1e30f;
                sP[(ty*4+i)*65 + tx*4 + j] = s;
            }
        __syncthreads();

        if (tid < 64) {
            int r = tid;
            float mold = sM[r];
            float mx = mold;
#pragma unroll 8
            for (int j = 0; j < 64; ++j) mx = fmaxf(mx, sP[r*65 + j]);
            float corr = __expf(mold - mx);
            float sum = 0.f;
#pragma unroll 8
            for (int j = 0; j < 64; ++j) {
                float p = __expf(sP[r*65 + j] - mx);
                sP[r*65 + j] = p;
                sum += p;
            }
            sM[r] = mx;
            sL[r] = sL[r]*corr + sum;
            sCorr[r] = corr;
        }
        __syncthreads();

#pragma unroll
        for (int r8 = 0; r8 < 8; ++r8) {
            float corr = sCorr[warp*8 + r8];
            o[r8][0] *= corr; o[r8][1] *= corr; o[r8][2] *= corr; o[r8][3] *= corr;
        }
        for (int j = 0; j < 64; ++j) {
            float4 vv = *(const float4*)&sV[j*128 + lane*4];
#pragma unroll
            for (int r8 = 0; r8 < 8; ++r8) {
                float p = sP[(warp*8 + r8)*65 + j];
                o[r8][0] += p*vv.x; o[r8][1] += p*vv.y;
                o[r8][2] += p*vv.z; o[r8][3] += p*vv.w;
            }
        }
    }

#pragma unroll
    for (int r8 = 0; r8 < 8; ++r8) {
        int row = qt*64 + warp*8 + r8;
        float inv = 1.0f / sL[warp*8 + r8];
        float4 res = make_float4(o[r8][0]*inv, o[r8][1]*inv, o[r8][2]*inv, o[r8][3]*inv);
        *(float4*)&ctx[((size_t)(b*SEQ + row))*DM + h*DKH + lane*4] = res;
    }
}

// ============================================================
extern "C" void kernel_launch(void* const* d_in, const int* in_sizes, int n_in,
                              void* d_out, int out_size)
{
    const float* x  = (const float*)d_in[0];
    const float* wq = (const float*)d_in[1];
    const float* wk = (const float*)d_in[2];
    const float* wv = (const float*)d_in[3];
    const float* wo = (const float*)d_in[4];
    const float* bo = (const float*)d_in[5];
    float* out = (float*)d_out;

    float *q, *k, *v, *ctx;
    __nv_bfloat16 *xh, *xl, *wh, *wl, *ch, *cl;
    cudaGetSymbolAddress((void**)&q,   g_q);
    cudaGetSymbolAddress((void**)&k,   g_k);
    cudaGetSymbolAddress((void**)&v,   g_v);
    cudaGetSymbolAddress((void**)&ctx, g_ctx);
    cudaGetSymbolAddress((void**)&xh,  g_xh);
    cudaGetSymbolAddress((void**)&xl,  g_xl);
    cudaGetSymbolAddress((void**)&wh,  g_wh);
    cudaGetSymbolAddress((void**)&wl,  g_wl);
    cudaGetSymbolAddress((void**)&ch,  g_ch);
    cudaGetSymbolAddress((void**)&cl,  g_cl);

    cudaFuncSetAttribute(gemm_mma<0>, cudaFuncAttributeMaxDynamicSharedMemorySize, GEMM_SMEM);
    cudaFuncSetAttribute(gemm_mma<1>, cudaFuncAttributeMaxDynamicSharedMemorySize, GEMM_SMEM);
    cudaFuncSetAttribute(attn_kernel, cudaFuncAttributeMaxDynamicSharedMemorySize, ATTN_SMEM_BYTES);

    const int NX4 = MTOT*DM/4;
    const int NW4 = DM*DM/4;

    split_kernel<<<NX4/256, 256>>>(x, xh, xl, NX4);
    split_kernel<<<NW4/256, 256>>>(wq, wh + 0*(size_t)DM*DM, wl + 0*(size_t)DM*DM, NW4);
    split_kernel<<<NW4/256, 256>>>(wk, wh + 1*(size_t)DM*DM, wl + 1*(size_t)DM*DM, NW4);
    split_kernel<<<NW4/256, 256>>>(wv, wh + 2*(size_t)DM*DM, wl + 2*(size_t)DM*DM, NW4);
    split_kernel<<<NW4/256, 256>>>(wo, wh + 3*(size_t)DM*DM, wl + 3*(size_t)DM*DM, NW4);

    dim3 gg(DM/BN, MTOT/BM);   // (16, 32)
    gemm_mma<0><<<gg, 256, GEMM_SMEM>>>(xh, xl, wh + 0*(size_t)DM*DM, wl + 0*(size_t)DM*DM, nullptr, q);
    gemm_mma<0><<<gg, 256, GEMM_SMEM>>>(xh, xl, wh + 1*(size_t)DM*DM, wl + 1*(size_t)DM*DM, nullptr, k);
    gemm_mma<0><<<gg, 256, GEMM_SMEM>>>(xh, xl, wh + 2*(size_t)DM*DM, wl + 2*(size_t)DM*DM, nullptr, v);

    rope_kernel<<<(BATCH*NH*SEQ*64 + 255)/256, 256>>>();

    attn_kernel<<<dim3(SEQ/64, BATCH*NH), 256, ATTN_SMEM_BYTES>>>(q, k, v, ctx);

    split_kernel<<<NX4/256, 256>>>(ctx, ch, cl, NX4);
    gemm_mma<1><<<gg, 256, GEMM_SMEM>>>(ch, cl, wh + 3*(size_t)DM*DM, wl + 3*(size_t)DM*DM, bo, out);
}

// round 5
// speedup vs baseline: 2.7753x; 1.4809x over previous
#include <cuda_runtime.h>
#include <cuda_bf16.h>
#include <math.h>
#include <stdint.h>

#define BATCH 2
#define SEQ   2048
#define DM    2048
#define NH    16
#define DKH   128
#define MTOT  (BATCH*SEQ)   // 4096
#define BH    (BATCH*NH)    // 32

// ---- scratch (device globals) ----
__device__ float g_q[MTOT*DM];
__device__ float g_k[MTOT*DM];
__device__ float g_v[MTOT*DM];
__device__ float g_ctx[MTOT*DM];
__device__ __nv_bfloat16 g_xh[MTOT*DM];
__device__ __nv_bfloat16 g_xl[MTOT*DM];
__device__ __nv_bfloat16 g_wh[4][DM*DM];
__device__ __nv_bfloat16 g_wl[4][DM*DM];
__device__ __nv_bfloat16 g_ch[MTOT*DM];
__device__ __nv_bfloat16 g_cl[MTOT*DM];
// attention operands
__device__ __nv_bfloat16 g_qh[BH*SEQ*DKH];
__device__ __nv_bfloat16 g_ql[BH*SEQ*DKH];
__device__ __nv_bfloat16 g_kh[BH*SEQ*DKH];
__device__ __nv_bfloat16 g_kl[BH*SEQ*DKH];
__device__ __nv_bfloat16 g_vth[BH*DKH*SEQ];
__device__ __nv_bfloat16 g_vtl[BH*DKH*SEQ];

// ============================================================
// helpers
// ============================================================
__device__ __forceinline__ uint32_t smem_u32(const void* p) {
    uint32_t a;
    asm("{ .reg .u64 t; cvta.to.shared.u64 t, %1; cvt.u32.u64 %0, t; }" : "=r"(a) : "l"(p));
    return a;
}
__device__ __forceinline__ void cp_async16(uint32_t dst, const void* src) {
    asm volatile("cp.async.cg.shared.global [%0], [%1], 16;" :: "r"(dst), "l"(src));
}
__device__ __forceinline__ void cp_commit() {
    asm volatile("cp.async.commit_group;" ::: "memory");
}
template<int N>
__device__ __forceinline__ void cp_wait() {
    asm volatile("cp.async.wait_group %0;" :: "n"(N) : "memory");
}
__device__ __forceinline__ void ldsm_x4(uint32_t& r0, uint32_t& r1, uint32_t& r2, uint32_t& r3, uint32_t a) {
    asm volatile("ldmatrix.sync.aligned.m8n8.x4.shared.b16 {%0,%1,%2,%3}, [%4];"
                 : "=r"(r0), "=r"(r1), "=r"(r2), "=r"(r3) : "r"(a));
}
__device__ __forceinline__ void ldsm_x2(uint32_t& r0, uint32_t& r1, uint32_t a) {
    asm volatile("ldmatrix.sync.aligned.m8n8.x2.shared.b16 {%0,%1}, [%2];"
                 : "=r"(r0), "=r"(r1) : "r"(a));
}
__device__ __forceinline__ void mma_bf16(float* c, const uint32_t* a, const uint32_t* b) {
    asm volatile("mma.sync.aligned.m16n8k16.row.col.f32.bf16.bf16.f32 "
                 "{%0,%1,%2,%3}, {%4,%5,%6,%7}, {%8,%9}, {%0,%1,%2,%3};"
                 : "+f"(c[0]), "+f"(c[1]), "+f"(c[2]), "+f"(c[3])
                 : "r"(a[0]), "r"(a[1]), "r"(a[2]), "r"(a[3]), "r"(b[0]), "r"(b[1]));
}
__device__ __forceinline__ uint32_t pack_bf2(float x, float y) {
    __nv_bfloat162 t(__float2bfloat16(x), __float2bfloat16(y));
    return *(uint32_t*)&t;
}

// ============================================================
// Split fp32 -> bf16 hi/lo
// ============================================================
__global__ __launch_bounds__(256)
void split_kernel(const float* __restrict__ src, __nv_bfloat16* __restrict__ hi,
                  __nv_bfloat16* __restrict__ lo, int n4)
{
    int i = blockIdx.x * 256 + threadIdx.x;
    if (i >= n4) return;
    float4 v = ((const float4*)src)[i];
    __nv_bfloat16 h0 = __float2bfloat16(v.x), h1 = __float2bfloat16(v.y);
    __nv_bfloat16 h2 = __float2bfloat16(v.z), h3 = __float2bfloat16(v.w);
    __nv_bfloat16 l0 = __float2bfloat16(v.x - __bfloat162float(h0));
    __nv_bfloat16 l1 = __float2bfloat16(v.y - __bfloat162float(h1));
    __nv_bfloat16 l2 = __float2bfloat16(v.z - __bfloat162float(h2));
    __nv_bfloat16 l3 = __float2bfloat16(v.w - __bfloat162float(h3));
    ((__nv_bfloat162*)hi)[2*i]   = __nv_bfloat162(h0, h1);
    ((__nv_bfloat162*)hi)[2*i+1] = __nv_bfloat162(h2, h3);
    ((__nv_bfloat162*)lo)[2*i]   = __nv_bfloat162(l0, l1);
    ((__nv_bfloat162*)lo)[2*i+1] = __nv_bfloat162(l2, l3);
}

// ============================================================
// mma.sync GEMM (unchanged from R3)
// ============================================================
#define BM 128
#define BN 128
#define BK 32
#define TSTRIDE 40
#define TILE_BYTES (128*TSTRIDE*2)
#define STAGE_BYTES (4*TILE_BYTES)
#define GEMM_SMEM (2*STAGE_BYTES)

template<int ADD_BIAS>
__global__ __launch_bounds__(256, 2)
void gemm_mma(const __nv_bfloat16* __restrict__ Ah, const __nv_bfloat16* __restrict__ Al,
              const __nv_bfloat16* __restrict__ Bh, const __nv_bfloat16* __restrict__ Bl,
              const float* __restrict__ bias, float* __restrict__ C)
{
    extern __shared__ __align__(128) char gsm[];
    const uint32_t sb = smem_u32(gsm);
    const int tid = threadIdx.x, wid = tid >> 5, lane = tid & 31;
    const int bm = blockIdx.y * BM;
    const int bn = blockIdx.x * BN;
    const int warp_m = wid >> 2;
    const int warp_n = wid & 3;
    const uint32_t OFF_AH = 0, OFF_AL = TILE_BYTES, OFF_BH = 2*TILE_BYTES, OFF_BL = 3*TILE_BYTES;

    float acc[4][4][4];
#pragma unroll
    for (int i = 0; i < 4; i++)
#pragma unroll
        for (int j = 0; j < 4; j++)
#pragma unroll
            for (int r = 0; r < 4; r++) acc[i][j][r] = 0.f;

    auto issue_chunk = [&](int c, int buf) {
        uint32_t st = sb + buf * STAGE_BYTES;
        int k0 = c * BK;
#pragma unroll
        for (int t = 0; t < 2; ++t) {
            int i = tid * 2 + t;
            int row = i >> 2, seg = i & 3;
            uint32_t dst = (uint32_t)(row * (TSTRIDE*2) + seg * 16);
            const char* ah = (const char*)(Ah + (size_t)(bm + row)*DM + k0) + seg*16;
            const char* al = (const char*)(Al + (size_t)(bm + row)*DM + k0) + seg*16;
            const char* wh = (const char*)(Bh + (size_t)(bn + row)*DM + k0) + seg*16;
            const char* wl = (const char*)(Bl + (size_t)(bn + row)*DM + k0) + seg*16;
            cp_async16(st + OFF_AH + dst, ah);
            cp_async16(st + OFF_AL + dst, al);
            cp_async16(st + OFF_BH + dst, wh);
            cp_async16(st + OFF_BL + dst, wl);
        }
        cp_commit();
    };

    issue_chunk(0, 0);

    const int NCH = DM / BK;
    for (int c = 0; c < NCH; ++c) {
        int buf = c & 1;
        if (c + 1 < NCH) { issue_chunk(c + 1, buf ^ 1); cp_wait<1>(); }
        else             { cp_wait<0>(); }
        __syncthreads();

        uint32_t st = sb + buf * STAGE_BYTES;
        uint32_t a_row = (uint32_t)(warp_m*64 + (lane & 15));
        uint32_t a_colb = (uint32_t)((lane >> 4) * 16);
        uint32_t b_row = (uint32_t)(warp_n*32 + (lane & 7));
        uint32_t b_colb = (uint32_t)(((lane >> 3) & 1) * 16);

#pragma unroll
        for (int kk = 0; kk < 2; ++kk) {
            uint32_t abase = st + a_row*(TSTRIDE*2) + kk*32 + a_colb;
            uint32_t bbase = st + b_row*(TSTRIDE*2) + kk*32 + b_colb;

            uint32_t ah[4][4], bh[4][2];
#pragma unroll
            for (int am = 0; am < 4; ++am)
                ldsm_x4(ah[am][0], ah[am][1], ah[am][2], ah[am][3],
                        abase + OFF_AH + am*16*(TSTRIDE*2));
#pragma unroll
            for (int bt = 0; bt < 4; ++bt)
                ldsm_x2(bh[bt][0], bh[bt][1], bbase + OFF_BH + bt*8*(TSTRIDE*2));
#pragma unroll
            for (int am = 0; am < 4; ++am)
#pragma unroll
                for (int bt = 0; bt < 4; ++bt)
                    mma_bf16(acc[am][bt], ah[am], bh[bt]);
            {
                uint32_t bl[4][2];
#pragma unroll
                for (int bt = 0; bt < 4; ++bt)
                    ldsm_x2(bl[bt][0], bl[bt][1], bbase + OFF_BL + bt*8*(TSTRIDE*2));
#pragma unroll
                for (int am = 0; am < 4; ++am)
#pragma unroll
                    for (int bt = 0; bt < 4; ++bt)
                        mma_bf16(acc[am][bt], ah[am], bl[bt]);
            }
            {
                uint32_t al[4][4];
#pragma unroll
                for (int am = 0; am < 4; ++am)
                    ldsm_x4(al[am][0], al[am][1], al[am][2], al[am][3],
                            abase + OFF_AL + am*16*(TSTRIDE*2));
#pragma unroll
                for (int am = 0; am < 4; ++am)
#pragma unroll
                    for (int bt = 0; bt < 4; ++bt)
                        mma_bf16(acc[am][bt], al[am], bh[bt]);
            }
        }
        __syncthreads();
    }

    const int m_base = bm + warp_m*64;
    const int n_base = bn + warp_n*32;
#pragma unroll
    for (int am = 0; am < 4; ++am) {
#pragma unroll
        for (int bt = 0; bt < 4; ++bt) {
            int col = n_base + bt*8 + (lane & 3)*2;
            int r0 = m_base + am*16 + (lane >> 2);
            float b0 = 0.f, b1 = 0.f;
            if (ADD_BIAS) { b0 = bias[col]; b1 = bias[col+1]; }
            float2 v0 = make_float2(acc[am][bt][0] + b0, acc[am][bt][1] + b1);
            float2 v1 = make_float2(acc[am][bt][2] + b0, acc[am][bt][3] + b1);
            *(float2*)(C + (size_t)r0*DM + col)       = v0;
            *(float2*)(C + (size_t)(r0+8)*DM + col)   = v1;
        }
    }
}

// ============================================================
// RoPE + split: fp32 q,k [b][s][h*128+dk] -> bf16 hi/lo [bh][s][dk]
// ============================================================
__global__ __launch_bounds__(256)
void rope_split_kernel()
{
    int idx = blockIdx.x * blockDim.x + threadIdx.x;
    const int total = BH*SEQ*64;
    if (idx >= total) return;
    int i  = idx & 63;
    int s  = (idx >> 6) & (SEQ-1);
    int bh = idx >> 17;
    int b = bh >> 4, h = bh & 15;
    size_t src = ((size_t)b*SEQ + s)*DM + h*DKH + 2*i;
    size_t dst = ((size_t)bh*SEQ + s)*DKH + 2*i;

    float freq = powf(10000.f, -((float)(2*i)) / 128.f);
    float ang  = (float)s * freq;
    float sn, cs;
    sincosf(ang, &sn, &cs);

    float qe = g_q[src], qo = g_q[src+1];
    float q0 = qe*cs - qo*sn, q1 = qe*sn + qo*cs;
    float ke = g_k[src], ko = g_k[src+1];
    float k0 = ke*cs - ko*sn, k1 = ke*sn + ko*cs;

    __nv_bfloat16 qh0 = __float2bfloat16(q0), qh1 = __float2bfloat16(q1);
    __nv_bfloat16 kh0 = __float2bfloat16(k0), kh1 = __float2bfloat16(k1);
    *(__nv_bfloat162*)&g_qh[dst] = __nv_bfloat162(qh0, qh1);
    *(__nv_bfloat162*)&g_ql[dst] = __nv_bfloat162(
        __float2bfloat16(q0 - __bfloat162float(qh0)),
        __float2bfloat16(q1 - __bfloat162float(qh1)));
    *(__nv_bfloat162*)&g_kh[dst] = __nv_bfloat162(kh0, kh1);
    *(__nv_bfloat162*)&g_kl[dst] = __nv_bfloat162(
        __float2bfloat16(k0 - __bfloat162float(kh0)),
        __float2bfloat16(k1 - __bfloat162float(kh1)));
}

// ============================================================
// V transpose+split: fp32 v [b][s][h*128+dk] -> bf16 [bh][dk][s]
// ============================================================
__global__ __launch_bounds__(256)
void vsplit_kernel()
{
    __shared__ float t[32][33];
    int dk0 = blockIdx.x * 32;
    int s0  = blockIdx.y * 32;
    int bh  = blockIdx.z;
    int b = bh >> 4, h = bh & 15;
    int tx = threadIdx.x & 31, ty = threadIdx.x >> 5;
#pragma unroll
    for (int r = 0; r < 4; ++r)
        t[ty + 8*r][tx] = g_v[((size_t)(b*SEQ) + s0 + ty + 8*r)*DM + h*DKH + dk0 + tx];
    __syncthreads();
#pragma unroll
    for (int r = 0; r < 4; ++r) {
        int dk = ty + 8*r;
        float val = t[tx][dk];
        __nv_bfloat16 hi = __float2bfloat16(val);
        size_t dst = ((size_t)bh*DKH + dk0 + dk)*SEQ + s0 + tx;
        g_vth[dst] = hi;
        g_vtl[dst] = __float2bfloat16(val - __bfloat162float(hi));
    }
}

// ============================================================
// Flash attention, bf16 mma, causal.
// CTA: 128 q-rows, kv tile 64.  8 warps x 16 q-rows.
// ============================================================
#define KSTRB 272
#define VSTRB 144
#define AQH 0
#define AQL 34816
#define AST0 69632
#define ASTAGE 71680
#define AKH 0
#define AKL 17408
#define AVTH 34816
#define AVTL 53248
#define ATTN_SMEM (AST0 + 2*ASTAGE)    // 212992

__global__ __launch_bounds__(256, 1)
void attn_mma(const __nv_bfloat16* __restrict__ qh, const __nv_bfloat16* __restrict__ ql,
              const __nv_bfloat16* __restrict__ kh, const __nv_bfloat16* __restrict__ kl,
              const __nv_bfloat16* __restrict__ vth, const __nv_bfloat16* __restrict__ vtl,
              float* __restrict__ ctx)
{
    extern __shared__ __align__(128) char asm_[];
    const uint32_t sb = smem_u32(asm_);
    const int qt = blockIdx.x;
    const int bh = blockIdx.y;
    const int tid = threadIdx.x, warp = tid >> 5, lane = tid & 31;
    const int b = bh >> 4, h = bh & 15;

    const __nv_bfloat16* qhb = qh + ((size_t)bh*SEQ + qt*128)*DKH;
    const __nv_bfloat16* qlb = ql + ((size_t)bh*SEQ + qt*128)*DKH;
    const __nv_bfloat16* khb = kh + (size_t)bh*SEQ*DKH;
    const __nv_bfloat16* klb = kl + (size_t)bh*SEQ*DKH;
    const __nv_bfloat16* vhb = vth + (size_t)bh*DKH*SEQ;
    const __nv_bfloat16* vlb = vtl + (size_t)bh*DKH*SEQ;

    // ---- load Q (group 0) ----
    for (int i = tid; i < 2048; i += 256) {
        int row = i >> 4, seg = i & 15;
        uint32_t dst = (uint32_t)(row * KSTRB + seg * 16);
        cp_async16(sb + AQH + dst, (const char*)(qhb + (size_t)row*DKH) + seg*16);
        cp_async16(sb + AQL + dst, (const char*)(qlb + (size_t)row*DKH) + seg*16);
    }
    cp_commit();

    auto issue_kv = [&](int kt, int buf) {
        uint32_t st = sb + AST0 + buf * ASTAGE;
        for (int i = tid; i < 1024; i += 256) {
            int row = i >> 4, seg = i & 15;
            uint32_t dst = (uint32_t)(row * KSTRB + seg * 16);
            const char* sk = (const char*)(khb + ((size_t)(kt*64) + row)*DKH) + seg*16;
            const char* sl = (const char*)(klb + ((size_t)(kt*64) + row)*DKH) + seg*16;
            cp_async16(st + AKH + dst, sk);
            cp_async16(st + AKL + dst, sl);
        }
        for (int i = tid; i < 1024; i += 256) {
            int row = i >> 3, seg = i & 7;
            uint32_t dst = (uint32_t)(row * VSTRB + seg * 16);
            const char* sv = (const char*)(vhb + (size_t)row*SEQ + kt*64) + seg*16;
            const char* sl = (const char*)(vlb + (size_t)row*SEQ + kt*64) + seg*16;
            cp_async16(st + AVTH + dst, sv);
            cp_async16(st + AVTL + dst, sl);
        }
        cp_commit();
    };

    const int nkt = 2*qt + 2;
    issue_kv(0, 0);

    float o[16][4];
#pragma unroll
    for (int i = 0; i < 16; i++)
#pragma unroll
        for (int j = 0; j < 4; j++) o[i][j] = 0.f;
    float m_[2] = {-1e30f, -1e30f};
    float l_[2] = {0.f, 0.f};

    const float scl = 0.08838834764831845f;
    const int row0g = qt*128 + warp*16 + (lane >> 2);

    const uint32_t a_off = (uint32_t)((warp*16 + (lane & 15)) * KSTRB + (lane >> 4) * 16);
    const uint32_t kb_rowsel = (uint32_t)((((lane >> 3) & 1) * 8 + (lane & 7)));
    const uint32_t kseg = (uint32_t)((lane >> 4) * 16);

    for (int kt = 0; kt < nkt; ++kt) {
        int buf = kt & 1;
        if (kt + 1 < nkt) { issue_kv(kt + 1, buf ^ 1); cp_wait<1>(); }
        else              { cp_wait<0>(); }
        __syncthreads();

        uint32_t st = sb + AST0 + buf * ASTAGE;

        // ---- S = Q K^T (3 passes) ----
        float s_[8][4];
#pragma unroll
        for (int i = 0; i < 8; i++)
#pragma unroll
            for (int j = 0; j < 4; j++) s_[i][j] = 0.f;

#pragma unroll
        for (int ks = 0; ks < 8; ++ks) {
            uint32_t aH[4], aL[4];
            ldsm_x4(aH[0], aH[1], aH[2], aH[3], sb + AQH + a_off + ks*32);
            ldsm_x4(aL[0], aL[1], aL[2], aL[3], sb + AQL + a_off + ks*32);
#pragma unroll
            for (int p = 0; p < 4; ++p) {
                uint32_t kaddr = st + (uint32_t)((p*16 + kb_rowsel) * KSTRB) + ks*32 + kseg;
                uint32_t r0, r1, r2, r3;
                ldsm_x4(r0, r1, r2, r3, kaddr + AKH);
                uint32_t bh0[2] = {r0, r2}, bh1[2] = {r1, r3};
                mma_bf16(s_[2*p],   aH, bh0);
                mma_bf16(s_[2*p+1], aH, bh1);
                mma_bf16(s_[2*p],   aL, bh0);
                mma_bf16(s_[2*p+1], aL, bh1);
                ldsm_x4(r0, r1, r2, r3, kaddr + AKL);
                uint32_t bl0[2] = {r0, r2}, bl1[2] = {r1, r3};
                mma_bf16(s_[2*p],   aH, bl0);
                mma_bf16(s_[2*p+1], aH, bl1);
            }
        }

        // ---- scale + causal mask ----
        // FIX (R4 bug): compare tile max col against warp MIN row (not max row).
        bool need_mask = (kt*64 + 63) > (qt*128 + warp*16);
#pragma unroll
        for (int nt = 0; nt < 8; ++nt) {
            int colg = kt*64 + nt*8 + (lane & 3)*2;
#pragma unroll
            for (int j = 0; j < 4; ++j) {
                float sv = s_[nt][j] * scl;
                if (need_mask) {
                    int r = row0g + ((j >> 1) << 3);
                    int c = colg + (j & 1);
                    if (c > r) sv = -1e30f;
                }
                s_[nt][j] = sv;
            }
        }

        // ---- online softmax (in-warp) ----
        float corr[2];
#pragma unroll
        for (int r = 0; r < 2; ++r) {
            float mx = m_[r];
#pragma unroll
            for (int nt = 0; nt < 8; ++nt)
                mx = fmaxf(mx, fmaxf(s_[nt][2*r], s_[nt][2*r+1]));
            mx = fmaxf(mx, __shfl_xor_sync(0xffffffffu, mx, 1));
            mx = fmaxf(mx, __shfl_xor_sync(0xffffffffu, mx, 2));
            corr[r] = __expf(m_[r] - mx);
            m_[r] = mx;
            float sum = 0.f;
#pragma unroll
            for (int nt = 0; nt < 8; ++nt) {
                float p0 = __expf(s_[nt][2*r]   - mx);
                float p1 = __expf(s_[nt][2*r+1] - mx);
                s_[nt][2*r] = p0; s_[nt][2*r+1] = p1;
                sum += p0 + p1;
            }
            sum += __shfl_xor_sync(0xffffffffu, sum, 1);
            sum += __shfl_xor_sync(0xffffffffu, sum, 2);
            l_[r] = l_[r]*corr[r] + sum;
        }

        // ---- pack P hi/lo ----
        uint32_t pH[8][2], pL[8][2];
#pragma unroll
        for (int nt = 0; nt < 8; ++nt) {
#pragma unroll
            for (int r = 0; r < 2; ++r) {
                float p0 = s_[nt][2*r], p1 = s_[nt][2*r+1];
                __nv_bfloat16 h0 = __float2bfloat16(p0), h1 = __float2bfloat16(p1);
                pH[nt][r] = pack_bf2(p0, p1);
                pL[nt][r] = pack_bf2(p0 - __bfloat162float(h0), p1 - __bfloat162float(h1));
            }
        }

        // ---- rescale O ----
#pragma unroll
        for (int dt = 0; dt < 16; ++dt) {
            o[dt][0] *= corr[0]; o[dt][1] *= corr[0];
            o[dt][2] *= corr[1]; o[dt][3] *= corr[1];
        }

        // ---- O += P V ----
#pragma unroll
        for (int kk = 0; kk < 4; ++kk) {
            uint32_t aP[4]  = {pH[2*kk][0], pH[2*kk][1], pH[2*kk+1][0], pH[2*kk+1][1]};
            uint32_t aPl[4] = {pL[2*kk][0], pL[2*kk][1], pL[2*kk+1][0], pL[2*kk+1][1]};
#pragma unroll
            for (int p = 0; p < 8; ++p) {
                uint32_t vaddr = st + (uint32_t)((p*16 + kb_rowsel) * VSTRB) + kk*32 + kseg;
                uint32_t r0, r1, r2, r3;
                ldsm_x4(r0, r1, r2, r3, vaddr + AVTH);
                uint32_t vh0[2] = {r0, r2}, vh1[2] = {r1, r3};
                mma_bf16(o[2*p],   aP,  vh0);
                mma_bf16(o[2*p+1], aP,  vh1);
                mma_bf16(o[2*p],   aPl, vh0);
                mma_bf16(o[2*p+1], aPl, vh1);
                ldsm_x4(r0, r1, r2, r3, vaddr + AVTL);
                uint32_t vl0[2] = {r0, r2}, vl1[2] = {r1, r3};
                mma_bf16(o[2*p],   aP, vl0);
                mma_bf16(o[2*p+1], aP, vl1);
            }
        }
        __syncthreads();
    }

    // ---- finalize ----
    float inv0 = 1.0f / l_[0], inv1 = 1.0f / l_[1];
    int r0 = qt*128 + warp*16 + (lane >> 2);
#pragma unroll
    for (int dt = 0; dt < 16; ++dt) {
        int col = h*DKH + dt*8 + (lane & 3)*2;
        *(float2*)&ctx[((size_t)(b*SEQ) + r0)*DM + col] =
            make_float2(o[dt][0]*inv0, o[dt][1]*inv0);
        *(float2*)&ctx[((size_t)(b*SEQ) + r0 + 8)*DM + col] =
            make_float2(o[dt][2]*inv1, o[dt][3]*inv1);
    }
}

// ============================================================
extern "C" void kernel_launch(void* const* d_in, const int* in_sizes, int n_in,
                              void* d_out, int out_size)
{
    const float* x  = (const float*)d_in[0];
    const float* wq = (const float*)d_in[1];
    const float* wk = (const float*)d_in[2];
    const float* wv = (const float*)d_in[3];
    const float* wo = (const float*)d_in[4];
    const float* bo = (const float*)d_in[5];
    float* out = (float*)d_out;

    float *q, *k, *v, *ctx;
    __nv_bfloat16 *xh, *xl, *wh, *wl, *ch, *cl;
    __nv_bfloat16 *qh, *ql, *kh, *kl, *vth, *vtl;
    cudaGetSymbolAddress((void**)&q,   g_q);
    cudaGetSymbolAddress((void**)&k,   g_k);
    cudaGetSymbolAddress((void**)&v,   g_v);
    cudaGetSymbolAddress((void**)&ctx, g_ctx);
    cudaGetSymbolAddress((void**)&xh,  g_xh);
    cudaGetSymbolAddress((void**)&xl,  g_xl);
    cudaGetSymbolAddress((void**)&wh,  g_wh);
    cudaGetSymbolAddress((void**)&wl,  g_wl);
    cudaGetSymbolAddress((void**)&ch,  g_ch);
    cudaGetSymbolAddress((void**)&cl,  g_cl);
    cudaGetSymbolAddress((void**)&qh,  g_qh);
    cudaGetSymbolAddress((void**)&ql,  g_ql);
    cudaGetSymbolAddress((void**)&kh,  g_kh);
    cudaGetSymbolAddress((void**)&kl,  g_kl);
    cudaGetSymbolAddress((void**)&vth, g_vth);
    cudaGetSymbolAddress((void**)&vtl, g_vtl);

    cudaFuncSetAttribute(gemm_mma<0>, cudaFuncAttributeMaxDynamicSharedMemorySize, GEMM_SMEM);
    cudaFuncSetAttribute(gemm_mma<1>, cudaFuncAttributeMaxDynamicSharedMemorySize, GEMM_SMEM);
    cudaFuncSetAttribute(attn_mma, cudaFuncAttributeMaxDynamicSharedMemorySize, ATTN_SMEM);

    const int NX4 = MTOT*DM/4;
    const int NW4 = DM*DM/4;

    split_kernel<<<NX4/256, 256>>>(x, xh, xl, NX4);
    split_kernel<<<NW4/256, 256>>>(wq, wh + 0*(size_t)DM*DM, wl + 0*(size_t)DM*DM, NW4);
    split_kernel<<<NW4/256, 256>>>(wk, wh + 1*(size_t)DM*DM, wl + 1*(size_t)DM*DM, NW4);
    split_kernel<<<NW4/256, 256>>>(wv, wh + 2*(size_t)DM*DM, wl + 2*(size_t)DM*DM, NW4);
    split_kernel<<<NW4/256, 256>>>(wo, wh + 3*(size_t)DM*DM, wl + 3*(size_t)DM*DM, NW4);

    dim3 gg(DM/BN, MTOT/BM);
    gemm_mma<0><<<gg, 256, GEMM_SMEM>>>(xh, xl, wh + 0*(size_t)DM*DM, wl + 0*(size_t)DM*DM, nullptr, q);
    gemm_mma<0><<<gg, 256, GEMM_SMEM>>>(xh, xl, wh + 1*(size_t)DM*DM, wl + 1*(size_t)DM*DM, nullptr, k);
    gemm_mma<0><<<gg, 256, GEMM_SMEM>>>(xh, xl, wh + 2*(size_t)DM*DM, wl + 2*(size_t)DM*DM, nullptr, v);

    rope_split_kernel<<<(BH*SEQ*64 + 255)/256, 256>>>();
    vsplit_kernel<<<dim3(DKH/32, SEQ/32, BH), 256>>>();

    attn_mma<<<dim3(SEQ/128, BH), 256, ATTN_SMEM>>>(qh, ql, kh, kl, vth, vtl, ctx);

    split_kernel<<<NX4/256, 256>>>(ctx, ch, cl, NX4);
    gemm_mma<1><<<gg, 256, GEMM_SMEM>>>(ch, cl, wh + 3*(size_t)DM*DM, wl + 3*(size_t)DM*DM, bo, out);
}